// round 5
// baseline (speedup 1.0000x reference)
#include <cuda_runtime.h>
#include <math.h>
#include <stdint.h>

// ---------------------------------------------------------------------------
// Problem constants: B=32, H=W=64, C=256, NH=8, hd=32, WS=8, SS=4, IM=4
// ---------------------------------------------------------------------------
#define M_TOK   131072
#define C_DIM   256
#define DFF     1024

// Scratch (device globals; no allocation at runtime)
__device__ float g_xw   [M_TOK * C_DIM];
__device__ float g_qkv  [M_TOK * 768];
__device__ float g_att  [M_TOK * C_DIM];
__device__ float g_hs   [M_TOK * C_DIM];
__device__ float g_y    [M_TOK * C_DIM];
__device__ float g_mid  [M_TOK * DFF];
__device__ float g_wqkv [C_DIM * 768];
__device__ float g_bqkv [768];

// ---------------------------------------------------------------------------
// cp.async helpers
// ---------------------------------------------------------------------------
__device__ __forceinline__ void cp_async16(void* smem, const void* gmem) {
    uint32_t s = (uint32_t)__cvta_generic_to_shared(smem);
    asm volatile("cp.async.cg.shared.global [%0], [%1], 16;\n" :: "r"(s), "l"(gmem));
}
__device__ __forceinline__ void cp_commit() {
    asm volatile("cp.async.commit_group;\n");
}
template<int N>
__device__ __forceinline__ void cp_wait() {
    asm volatile("cp.async.wait_group %0;\n" :: "n"(N));
}

// ---------------------------------------------------------------------------
// Pack wq|wk|wv -> [256,768], bq|bk|bv -> [768]
// ---------------------------------------------------------------------------
__global__ __launch_bounds__(256) void pack_qkv(
    const float* __restrict__ wq, const float* __restrict__ wk,
    const float* __restrict__ wv, const float* __restrict__ bq,
    const float* __restrict__ bk, const float* __restrict__ bv,
    float* __restrict__ wdst, float* __restrict__ bdst)
{
    int idx = blockIdx.x * 256 + threadIdx.x;       // 0 .. 196607
    int k = idx / 768, n = idx % 768;
    float v = (n < 256) ? wq[k * 256 + n]
            : (n < 512) ? wk[k * 256 + n - 256]
                        : wv[k * 256 + n - 512];
    wdst[idx] = v;
    if (idx < 768)
        bdst[idx] = (idx < 256) ? bq[idx] : (idx < 512) ? bk[idx - 256] : bv[idx - 512];
}

// ---------------------------------------------------------------------------
// LayerNorm: warp-per-token, 8 tokens/block, float4 I/O.
// gather=1: read through inverse (roll -4,-4 + window partition) mapping.
// ---------------------------------------------------------------------------
__global__ __launch_bounds__(256) void ln_kernel(
    const float* __restrict__ x, const float* __restrict__ g,
    const float* __restrict__ bb, float* __restrict__ out, int gather)
{
    int warp = threadIdx.x >> 5, lane = threadIdx.x & 31;
    int r = blockIdx.x * 8 + warp;
    long src;
    if (gather) {
        int b  = r >> 12;
        int wi = (r >> 9) & 7, wj = (r >> 6) & 7;
        int pi = (r >> 3) & 7, pj = r & 7;
        int h = (wi * 8 + pi + 4) & 63;
        int w = (wj * 8 + pj + 4) & 63;
        src = (long)b * 4096 + h * 64 + w;
    } else {
        src = r;
    }
    const float4* xp = (const float4*)(x + src * C_DIM);
    float4 v0 = xp[lane * 2], v1 = xp[lane * 2 + 1];
    float s  = v0.x + v0.y + v0.z + v0.w + v1.x + v1.y + v1.z + v1.w;
    float s2 = v0.x*v0.x + v0.y*v0.y + v0.z*v0.z + v0.w*v0.w
             + v1.x*v1.x + v1.y*v1.y + v1.z*v1.z + v1.w*v1.w;
    #pragma unroll
    for (int o = 16; o > 0; o >>= 1) {
        s  += __shfl_xor_sync(0xffffffffu, s, o);
        s2 += __shfl_xor_sync(0xffffffffu, s2, o);
    }
    float mean = s * (1.f / 256.f);
    float var  = s2 * (1.f / 256.f) - mean * mean;
    float rstd = rsqrtf(var + 1e-5f);
    const float4* gp = (const float4*)(g  + lane * 8);
    const float4* bp = (const float4*)(bb + lane * 8);
    float4 g0 = gp[0], g1 = gp[1], b0 = bp[0], b1 = bp[1];
    float4 o0, o1;
    o0.x = (v0.x - mean) * rstd * g0.x + b0.x;
    o0.y = (v0.y - mean) * rstd * g0.y + b0.y;
    o0.z = (v0.z - mean) * rstd * g0.z + b0.z;
    o0.w = (v0.w - mean) * rstd * g0.w + b0.w;
    o1.x = (v1.x - mean) * rstd * g1.x + b1.x;
    o1.y = (v1.y - mean) * rstd * g1.y + b1.y;
    o1.z = (v1.z - mean) * rstd * g1.z + b1.z;
    o1.w = (v1.w - mean) * rstd * g1.w + b1.w;
    float4* op = (float4*)(out + (long)r * C_DIM + lane * 8);
    op[0] = o0; op[1] = o1;
}

// ---------------------------------------------------------------------------
// TF32 tensor-core GEMM: C = epi(A[MxK] @ B[KxN] + bias)
// EPI: 0 plain, 1 GELU, 2 scatter(window-reverse+roll)+residual, 3 residual.
// Block 128x256, BK=16, 3-stage cp.async, 8 warps (2m x 4n), warp tile 64x64.
// Conflict-free fragment strides: ASTR=20 (mod32=20), BSTR=264 (mod32=8).
// ---------------------------------------------------------------------------
#define NSTG 3
#define BM   128
#define BN   256
#define ASTR 20
#define BSTR 264
#define A_STAGE (BM * ASTR)    // 2560 floats
#define B_STAGE (16 * BSTR)    // 4224 floats
#define SMEM_SZ ((NSTG * (A_STAGE + B_STAGE)) * 4)   // 81408 bytes

__device__ __forceinline__ void mma_tf32(float d[4], const uint32_t a[4], const uint32_t b[2]) {
    asm volatile(
        "mma.sync.aligned.m16n8k8.row.col.f32.tf32.tf32.f32 "
        "{%0,%1,%2,%3}, {%4,%5,%6,%7}, {%8,%9}, {%0,%1,%2,%3};\n"
        : "+f"(d[0]), "+f"(d[1]), "+f"(d[2]), "+f"(d[3])
        : "r"(a[0]), "r"(a[1]), "r"(a[2]), "r"(a[3]), "r"(b[0]), "r"(b[1]));
}

template<int EPI>
__global__ __launch_bounds__(256, 1) void tf32gemm(
    const float* __restrict__ A, const float* __restrict__ B,
    const float* __restrict__ bias, const float* __restrict__ R,
    float* __restrict__ C, int M, int N, int K)
{
    extern __shared__ float sm[];
    float* Asm = sm;
    float* Bsm = sm + NSTG * A_STAGE;

    int tid  = threadIdx.x;
    int lane = tid & 31, warp = tid >> 5;
    int wm = warp >> 2, wn = warp & 3;      // 2 (m) x 4 (n)
    int bm = blockIdx.y * BM, bn = blockIdx.x * BN;
    int gid = lane >> 2, tig = lane & 3;

    float acc[4][8][4];
    #pragma unroll
    for (int mt = 0; mt < 4; mt++)
        #pragma unroll
        for (int nt = 0; nt < 8; nt++)
            #pragma unroll
            for (int i = 0; i < 4; i++) acc[mt][nt][i] = 0.f;

    // A: 128x16 = 512 float4 segs (2/thread); B: 16x256 = 1024 segs (4/thread)
    int aR[2], aC[2], bR[4], bC[4];
    #pragma unroll
    for (int i = 0; i < 2; i++) {
        int s = tid + i * 256;
        aR[i] = s >> 2;  aC[i] = (s & 3) * 4;
    }
    #pragma unroll
    for (int i = 0; i < 4; i++) {
        int s = tid + i * 256;
        bR[i] = s >> 6;  bC[i] = (s & 63) * 4;
    }

    int KT = K >> 4;

    #pragma unroll
    for (int s = 0; s < NSTG - 1; s++) {
        int kb = s << 4;
        float* as = Asm + s * A_STAGE;
        float* bs = Bsm + s * B_STAGE;
        #pragma unroll
        for (int i = 0; i < 2; i++)
            cp_async16(&as[aR[i] * ASTR + aC[i]], A + (long)(bm + aR[i]) * K + kb + aC[i]);
        #pragma unroll
        for (int i = 0; i < 4; i++)
            cp_async16(&bs[bR[i] * BSTR + bC[i]], B + (long)(kb + bR[i]) * N + bn + bC[i]);
        cp_commit();
    }

    for (int kt = 0; kt < KT; kt++) {
        if (kt + NSTG - 1 < KT) cp_wait<NSTG - 2>(); else cp_wait<0>();
        __syncthreads();
        int stg = kt % NSTG;
        const float* as = Asm + stg * A_STAGE;
        const float* bs = Bsm + stg * B_STAGE;
        #pragma unroll
        for (int ks = 0; ks < 2; ks++) {
            uint32_t af[4][4], bf[8][2];
            #pragma unroll
            for (int mt = 0; mt < 4; mt++) {
                int r0 = wm * 64 + mt * 16 + gid;
                int c0 = ks * 8 + tig;
                af[mt][0] = __float_as_uint(as[r0 * ASTR + c0]);
                af[mt][1] = __float_as_uint(as[(r0 + 8) * ASTR + c0]);
                af[mt][2] = __float_as_uint(as[r0 * ASTR + c0 + 4]);
                af[mt][3] = __float_as_uint(as[(r0 + 8) * ASTR + c0 + 4]);
            }
            #pragma unroll
            for (int nt = 0; nt < 8; nt++) {
                int rr = ks * 8 + tig;
                int cc = wn * 64 + nt * 8 + gid;
                bf[nt][0] = __float_as_uint(bs[rr * BSTR + cc]);
                bf[nt][1] = __float_as_uint(bs[(rr + 4) * BSTR + cc]);
            }
            #pragma unroll
            for (int mt = 0; mt < 4; mt++)
                #pragma unroll
                for (int nt = 0; nt < 8; nt++)
                    mma_tf32(acc[mt][nt], af[mt], bf[nt]);
        }
        // Load stage kt+NSTG-1 into buffer (kt-1)%NSTG: all warps finished
        // computing that buffer before the __syncthreads above.
        if (kt + NSTG - 1 < KT) {
            int kn = kt + NSTG - 1;
            int kb = kn << 4;
            int ds = kn % NSTG;
            float* asn = Asm + ds * A_STAGE;
            float* bsn = Bsm + ds * B_STAGE;
            #pragma unroll
            for (int i = 0; i < 2; i++)
                cp_async16(&asn[aR[i] * ASTR + aC[i]], A + (long)(bm + aR[i]) * K + kb + aC[i]);
            #pragma unroll
            for (int i = 0; i < 4; i++)
                cp_async16(&bsn[bR[i] * BSTR + bC[i]], B + (long)(kb + bR[i]) * N + bn + bC[i]);
            cp_commit();
        }
    }

    // epilogue
    #pragma unroll
    for (int mt = 0; mt < 4; mt++) {
        #pragma unroll
        for (int half = 0; half < 2; half++) {
            int row = bm + wm * 64 + mt * 16 + half * 8 + gid;
            long orow;
            if (EPI == 2) {
                int b  = row >> 12;
                int wi = (row >> 9) & 7, wj = (row >> 6) & 7;
                int pi = (row >> 3) & 7, pj = row & 7;
                int h = (wi * 8 + pi + 4) & 63;
                int w = (wj * 8 + pj + 4) & 63;
                orow = (long)b * 4096 + h * 64 + w;
            } else {
                orow = row;
            }
            #pragma unroll
            for (int nt = 0; nt < 8; nt++) {
                int col = bn + wn * 64 + nt * 8 + 2 * tig;
                float v0 = acc[mt][nt][half * 2 + 0] + bias[col];
                float v1 = acc[mt][nt][half * 2 + 1] + bias[col + 1];
                if (EPI == 1) {
                    v0 = 0.5f * v0 * (1.f + erff(v0 * 0.70710678118654752f));
                    v1 = 0.5f * v1 * (1.f + erff(v1 * 0.70710678118654752f));
                }
                if (EPI == 2 || EPI == 3) {
                    float2 rr = *(const float2*)(R + orow * N + col);
                    v0 += rr.x; v1 += rr.y;
                }
                float2 o; o.x = v0; o.y = v1;
                *(float2*)(C + orow * N + col) = o;
            }
        }
    }
}

// ---------------------------------------------------------------------------
// Fused windowed attention: QKV fused buffer (stride 768), output stride 256.
// ---------------------------------------------------------------------------
__device__ __forceinline__ int bandf(int z) { return z < 56 ? 0 : (z < 60 ? 1 : 2); }

__global__ __launch_bounds__(256) void attn_kernel(
    const float* __restrict__ QKV, const float* __restrict__ bt,
    float* __restrict__ O)
{
    __shared__ float Qs[64][33];
    __shared__ float Ks[64][33];
    __shared__ float Vs[64][33];
    __shared__ float Ps[64][65];

    int win  = blockIdx.x;
    int head = blockIdx.y;
    int t = threadIdx.x;
    long base = (long)win * 64 * 768 + head * 32;

    #pragma unroll
    for (int i = 0; i < 2; i++) {
        int idx = t + i * 256;
        int row = idx >> 3, c4 = (idx & 7) * 4;
        const float* src = QKV + base + (long)row * 768 + c4;
        float4 q4 = *(const float4*)(src);
        float4 k4 = *(const float4*)(src + 256);
        float4 v4 = *(const float4*)(src + 512);
        Qs[row][c4] = q4.x; Qs[row][c4+1] = q4.y; Qs[row][c4+2] = q4.z; Qs[row][c4+3] = q4.w;
        Ks[row][c4] = k4.x; Ks[row][c4+1] = k4.y; Ks[row][c4+2] = k4.z; Ks[row][c4+3] = k4.w;
        Vs[row][c4] = v4.x; Vs[row][c4+1] = v4.y; Vs[row][c4+2] = v4.z; Vs[row][c4+3] = v4.w;
    }
    __syncthreads();

    int row = t >> 2, l = t & 3;
    float qreg[32];
    #pragma unroll
    for (int kk = 0; kk < 32; kk++) qreg[kk] = Qs[row][kk];

    int yi = row >> 3, xi = row & 7;
    int w_in_b = win & 63;
    int wwi = w_in_b >> 3, wwj = w_in_b & 7;
    bool edge = (wwi == 7) || (wwj == 7);
    int id_i = 0;
    if (edge) id_i = bandf(wwi * 8 + yi) * 3 + bandf(wwj * 8 + xi);

    const float scale = 0.17677669529663687f;
    float sreg[16];
    float mx = -1e30f;
    #pragma unroll
    for (int c = 0; c < 16; c++) {
        int col = c * 4 + l;
        float s = 0.f;
        #pragma unroll
        for (int kk = 0; kk < 32; kk++) s = fmaf(qreg[kk], Ks[col][kk], s);
        s *= scale;
        int yj = col >> 3, xj = col & 7;
        s += bt[((yi - yj + 7) * 15 + (xi - xj + 7)) * 8 + head];
        if (edge) {
            int id_j = bandf(wwi * 8 + yj) * 3 + bandf(wwj * 8 + xj);
            if (id_i != id_j) s -= 100.f;
        }
        sreg[c] = s;
        mx = fmaxf(mx, s);
    }
    mx = fmaxf(mx, __shfl_xor_sync(0xffffffffu, mx, 1));
    mx = fmaxf(mx, __shfl_xor_sync(0xffffffffu, mx, 2));

    float sum = 0.f;
    #pragma unroll
    for (int c = 0; c < 16; c++) {
        float p = expf(sreg[c] - mx);
        sum += p;
        Ps[row][c * 4 + l] = p;
    }
    sum += __shfl_xor_sync(0xffffffffu, sum, 1);
    sum += __shfl_xor_sync(0xffffffffu, sum, 2);
    float rs = 1.f / sum;
    __syncthreads();

    float o[8];
    #pragma unroll
    for (int d = 0; d < 8; d++) o[d] = 0.f;
    #pragma unroll
    for (int col = 0; col < 64; col++) {
        float p = Ps[row][col];
        #pragma unroll
        for (int d = 0; d < 8; d++)
            o[d] = fmaf(p, Vs[col][l * 8 + d], o[d]);
    }
    float* op = O + ((long)win * 64 + row) * C_DIM + head * 32 + l * 8;
    float4 o0, o1;
    o0.x = o[0]*rs; o0.y = o[1]*rs; o0.z = o[2]*rs; o0.w = o[3]*rs;
    o1.x = o[4]*rs; o1.y = o[5]*rs; o1.z = o[6]*rs; o1.w = o[7]*rs;
    *(float4*)(op)     = o0;
    *(float4*)(op + 4) = o1;
}

// ---------------------------------------------------------------------------
// Launch
// ---------------------------------------------------------------------------
extern "C" void kernel_launch(void* const* d_in, const int* in_sizes, int n_in,
                              void* d_out, int out_size)
{
    const float* hidden = (const float*)d_in[0];
    const float* ln1_g  = (const float*)d_in[1];
    const float* ln1_b  = (const float*)d_in[2];
    const float* wq     = (const float*)d_in[3];
    const float* bq     = (const float*)d_in[4];
    const float* wk     = (const float*)d_in[5];
    const float* bk     = (const float*)d_in[6];
    const float* wv     = (const float*)d_in[7];
    const float* bv     = (const float*)d_in[8];
    const float* bt     = (const float*)d_in[9];
    const float* wo     = (const float*)d_in[10];
    const float* bo     = (const float*)d_in[11];
    const float* ln2_g  = (const float*)d_in[12];
    const float* ln2_b  = (const float*)d_in[13];
    const float* w1     = (const float*)d_in[14];
    const float* b1     = (const float*)d_in[15];
    const float* w2     = (const float*)d_in[16];
    const float* b2     = (const float*)d_in[17];
    float* out = (float*)d_out;

    float *p_xw, *p_qkv, *p_att, *p_hs, *p_y, *p_mid, *p_wqkv, *p_bqkv;
    cudaGetSymbolAddress((void**)&p_xw,   g_xw);
    cudaGetSymbolAddress((void**)&p_qkv,  g_qkv);
    cudaGetSymbolAddress((void**)&p_att,  g_att);
    cudaGetSymbolAddress((void**)&p_hs,   g_hs);
    cudaGetSymbolAddress((void**)&p_y,    g_y);
    cudaGetSymbolAddress((void**)&p_mid,  g_mid);
    cudaGetSymbolAddress((void**)&p_wqkv, g_wqkv);
    cudaGetSymbolAddress((void**)&p_bqkv, g_bqkv);

    cudaFuncSetAttribute(tf32gemm<0>, cudaFuncAttributeMaxDynamicSharedMemorySize, SMEM_SZ);
    cudaFuncSetAttribute(tf32gemm<1>, cudaFuncAttributeMaxDynamicSharedMemorySize, SMEM_SZ);
    cudaFuncSetAttribute(tf32gemm<2>, cudaFuncAttributeMaxDynamicSharedMemorySize, SMEM_SZ);
    cudaFuncSetAttribute(tf32gemm<3>, cudaFuncAttributeMaxDynamicSharedMemorySize, SMEM_SZ);

    dim3 blk(256);

    // 0. pack QKV weights/bias
    pack_qkv<<<768, blk>>>(wq, wk, wv, bq, bk, bv, p_wqkv, p_bqkv);

    // 1. LN1 + cyclic shift + window partition
    ln_kernel<<<M_TOK / 8, blk>>>(hidden, ln1_g, ln1_b, p_xw, 1);

    // 2. fused QKV projection (N=768)
    tf32gemm<0><<<dim3(768 / BN, M_TOK / BM), blk, SMEM_SZ>>>(
        p_xw, p_wqkv, p_bqkv, nullptr, p_qkv, M_TOK, 768, C_DIM);

    // 3. fused windowed attention
    attn_kernel<<<dim3(2048, 8), blk>>>(p_qkv, bt, p_att);

    // 4. output projection + window reverse + roll + residual -> hs
    tf32gemm<2><<<dim3(C_DIM / BN, M_TOK / BM), blk, SMEM_SZ>>>(
        p_att, wo, bo, hidden, p_hs, M_TOK, C_DIM, C_DIM);

    // 5. LN2
    ln_kernel<<<M_TOK / 8, blk>>>(p_hs, ln2_g, ln2_b, p_y, 0);

    // 6. MLP fc1 + exact GELU
    tf32gemm<1><<<dim3(DFF / BN, M_TOK / BM), blk, SMEM_SZ>>>(
        p_y, w1, b1, nullptr, p_mid, M_TOK, DFF, C_DIM);

    // 7. MLP fc2 + residual -> out
    tf32gemm<3><<<dim3(C_DIM / BN, M_TOK / BM), blk, SMEM_SZ>>>(
        p_mid, w2, b2, p_hs, out, M_TOK, C_DIM, DFF);
}

// round 6
// speedup vs baseline: 1.0359x; 1.0359x over previous
#include <cuda_runtime.h>
#include <math.h>
#include <stdint.h>

// ---------------------------------------------------------------------------
// Problem constants: B=32, H=W=64, C=256, NH=8, hd=32, WS=8, SS=4, IM=4
// ---------------------------------------------------------------------------
#define M_TOK   131072
#define C_DIM   256
#define DFF     1024

// Scratch (device globals; no allocation at runtime)
__device__ float g_xw   [M_TOK * C_DIM];
__device__ float g_qkv  [M_TOK * 768];
__device__ float g_att  [M_TOK * C_DIM];
__device__ float g_hs   [M_TOK * C_DIM];
__device__ float g_y    [M_TOK * C_DIM];
__device__ float g_mid  [M_TOK * DFF];
__device__ float g_wqkv [C_DIM * 768];
__device__ float g_bqkv [768];

// ---------------------------------------------------------------------------
// cp.async helpers
// ---------------------------------------------------------------------------
__device__ __forceinline__ void cp_async16(void* smem, const void* gmem) {
    uint32_t s = (uint32_t)__cvta_generic_to_shared(smem);
    asm volatile("cp.async.cg.shared.global [%0], [%1], 16;\n" :: "r"(s), "l"(gmem));
}
__device__ __forceinline__ void cp_commit() {
    asm volatile("cp.async.commit_group;\n");
}
template<int N>
__device__ __forceinline__ void cp_wait() {
    asm volatile("cp.async.wait_group %0;\n" :: "n"(N));
}

// ---------------------------------------------------------------------------
// Pack wq|wk|wv -> [256,768], bq|bk|bv -> [768]
// ---------------------------------------------------------------------------
__global__ __launch_bounds__(256) void pack_qkv(
    const float* __restrict__ wq, const float* __restrict__ wk,
    const float* __restrict__ wv, const float* __restrict__ bq,
    const float* __restrict__ bk, const float* __restrict__ bv,
    float* __restrict__ wdst, float* __restrict__ bdst)
{
    int idx = blockIdx.x * 256 + threadIdx.x;
    int k = idx / 768, n = idx % 768;
    float v = (n < 256) ? wq[k * 256 + n]
            : (n < 512) ? wk[k * 256 + n - 256]
                        : wv[k * 256 + n - 512];
    wdst[idx] = v;
    if (idx < 768)
        bdst[idx] = (idx < 256) ? bq[idx] : (idx < 512) ? bk[idx - 256] : bv[idx - 512];
}

// ---------------------------------------------------------------------------
// LayerNorm: warp-per-token, 8 tokens/block, float4 I/O.
// ---------------------------------------------------------------------------
__global__ __launch_bounds__(256) void ln_kernel(
    const float* __restrict__ x, const float* __restrict__ g,
    const float* __restrict__ bb, float* __restrict__ out, int gather)
{
    int warp = threadIdx.x >> 5, lane = threadIdx.x & 31;
    int r = blockIdx.x * 8 + warp;
    long src;
    if (gather) {
        int b  = r >> 12;
        int wi = (r >> 9) & 7, wj = (r >> 6) & 7;
        int pi = (r >> 3) & 7, pj = r & 7;
        int h = (wi * 8 + pi + 4) & 63;
        int w = (wj * 8 + pj + 4) & 63;
        src = (long)b * 4096 + h * 64 + w;
    } else {
        src = r;
    }
    const float4* xp = (const float4*)(x + src * C_DIM);
    float4 v0 = xp[lane * 2], v1 = xp[lane * 2 + 1];
    float s  = v0.x + v0.y + v0.z + v0.w + v1.x + v1.y + v1.z + v1.w;
    float s2 = v0.x*v0.x + v0.y*v0.y + v0.z*v0.z + v0.w*v0.w
             + v1.x*v1.x + v1.y*v1.y + v1.z*v1.z + v1.w*v1.w;
    #pragma unroll
    for (int o = 16; o > 0; o >>= 1) {
        s  += __shfl_xor_sync(0xffffffffu, s, o);
        s2 += __shfl_xor_sync(0xffffffffu, s2, o);
    }
    float mean = s * (1.f / 256.f);
    float var  = s2 * (1.f / 256.f) - mean * mean;
    float rstd = rsqrtf(var + 1e-5f);
    const float4* gp = (const float4*)(g  + lane * 8);
    const float4* bp = (const float4*)(bb + lane * 8);
    float4 g0 = gp[0], g1 = gp[1], b0 = bp[0], b1 = bp[1];
    float4 o0, o1;
    o0.x = (v0.x - mean) * rstd * g0.x + b0.x;
    o0.y = (v0.y - mean) * rstd * g0.y + b0.y;
    o0.z = (v0.z - mean) * rstd * g0.z + b0.z;
    o0.w = (v0.w - mean) * rstd * g0.w + b0.w;
    o1.x = (v1.x - mean) * rstd * g1.x + b1.x;
    o1.y = (v1.y - mean) * rstd * g1.y + b1.y;
    o1.z = (v1.z - mean) * rstd * g1.z + b1.z;
    o1.w = (v1.w - mean) * rstd * g1.w + b1.w;
    float4* op = (float4*)(out + (long)r * C_DIM + lane * 8);
    op[0] = o0; op[1] = o1;
}

// ---------------------------------------------------------------------------
// TF32 tensor-core GEMM (unchanged from Round 5)
// ---------------------------------------------------------------------------
#define NSTG 3
#define BM   128
#define BN   256
#define ASTR 20
#define BSTR 264
#define A_STAGE (BM * ASTR)
#define B_STAGE (16 * BSTR)
#define SMEM_SZ ((NSTG * (A_STAGE + B_STAGE)) * 4)

__device__ __forceinline__ void mma_tf32(float d[4], const uint32_t a[4], const uint32_t b[2]) {
    asm volatile(
        "mma.sync.aligned.m16n8k8.row.col.f32.tf32.tf32.f32 "
        "{%0,%1,%2,%3}, {%4,%5,%6,%7}, {%8,%9}, {%0,%1,%2,%3};\n"
        : "+f"(d[0]), "+f"(d[1]), "+f"(d[2]), "+f"(d[3])
        : "r"(a[0]), "r"(a[1]), "r"(a[2]), "r"(a[3]), "r"(b[0]), "r"(b[1]));
}

template<int EPI>
__global__ __launch_bounds__(256, 1) void tf32gemm(
    const float* __restrict__ A, const float* __restrict__ B,
    const float* __restrict__ bias, const float* __restrict__ R,
    float* __restrict__ C, int M, int N, int K)
{
    extern __shared__ float sm[];
    float* Asm = sm;
    float* Bsm = sm + NSTG * A_STAGE;

    int tid  = threadIdx.x;
    int lane = tid & 31, warp = tid >> 5;
    int wm = warp >> 2, wn = warp & 3;
    int bm = blockIdx.y * BM, bn = blockIdx.x * BN;
    int gid = lane >> 2, tig = lane & 3;

    float acc[4][8][4];
    #pragma unroll
    for (int mt = 0; mt < 4; mt++)
        #pragma unroll
        for (int nt = 0; nt < 8; nt++)
            #pragma unroll
            for (int i = 0; i < 4; i++) acc[mt][nt][i] = 0.f;

    int aR[2], aC[2], bR[4], bC[4];
    #pragma unroll
    for (int i = 0; i < 2; i++) {
        int s = tid + i * 256;
        aR[i] = s >> 2;  aC[i] = (s & 3) * 4;
    }
    #pragma unroll
    for (int i = 0; i < 4; i++) {
        int s = tid + i * 256;
        bR[i] = s >> 6;  bC[i] = (s & 63) * 4;
    }

    int KT = K >> 4;

    #pragma unroll
    for (int s = 0; s < NSTG - 1; s++) {
        int kb = s << 4;
        float* as = Asm + s * A_STAGE;
        float* bs = Bsm + s * B_STAGE;
        #pragma unroll
        for (int i = 0; i < 2; i++)
            cp_async16(&as[aR[i] * ASTR + aC[i]], A + (long)(bm + aR[i]) * K + kb + aC[i]);
        #pragma unroll
        for (int i = 0; i < 4; i++)
            cp_async16(&bs[bR[i] * BSTR + bC[i]], B + (long)(kb + bR[i]) * N + bn + bC[i]);
        cp_commit();
    }

    for (int kt = 0; kt < KT; kt++) {
        if (kt + NSTG - 1 < KT) cp_wait<NSTG - 2>(); else cp_wait<0>();
        __syncthreads();
        int stg = kt % NSTG;
        const float* as = Asm + stg * A_STAGE;
        const float* bs = Bsm + stg * B_STAGE;
        #pragma unroll
        for (int ks = 0; ks < 2; ks++) {
            uint32_t af[4][4], bf[8][2];
            #pragma unroll
            for (int mt = 0; mt < 4; mt++) {
                int r0 = wm * 64 + mt * 16 + gid;
                int c0 = ks * 8 + tig;
                af[mt][0] = __float_as_uint(as[r0 * ASTR + c0]);
                af[mt][1] = __float_as_uint(as[(r0 + 8) * ASTR + c0]);
                af[mt][2] = __float_as_uint(as[r0 * ASTR + c0 + 4]);
                af[mt][3] = __float_as_uint(as[(r0 + 8) * ASTR + c0 + 4]);
            }
            #pragma unroll
            for (int nt = 0; nt < 8; nt++) {
                int rr = ks * 8 + tig;
                int cc = wn * 64 + nt * 8 + gid;
                bf[nt][0] = __float_as_uint(bs[rr * BSTR + cc]);
                bf[nt][1] = __float_as_uint(bs[(rr + 4) * BSTR + cc]);
            }
            #pragma unroll
            for (int mt = 0; mt < 4; mt++)
                #pragma unroll
                for (int nt = 0; nt < 8; nt++)
                    mma_tf32(acc[mt][nt], af[mt], bf[nt]);
        }
        if (kt + NSTG - 1 < KT) {
            int kn = kt + NSTG - 1;
            int kb = kn << 4;
            int ds = kn % NSTG;
            float* asn = Asm + ds * A_STAGE;
            float* bsn = Bsm + ds * B_STAGE;
            #pragma unroll
            for (int i = 0; i < 2; i++)
                cp_async16(&asn[aR[i] * ASTR + aC[i]], A + (long)(bm + aR[i]) * K + kb + aC[i]);
            #pragma unroll
            for (int i = 0; i < 4; i++)
                cp_async16(&bsn[bR[i] * BSTR + bC[i]], B + (long)(kb + bR[i]) * N + bn + bC[i]);
            cp_commit();
        }
    }

    #pragma unroll
    for (int mt = 0; mt < 4; mt++) {
        #pragma unroll
        for (int half = 0; half < 2; half++) {
            int row = bm + wm * 64 + mt * 16 + half * 8 + gid;
            long orow;
            if (EPI == 2) {
                int b  = row >> 12;
                int wi = (row >> 9) & 7, wj = (row >> 6) & 7;
                int pi = (row >> 3) & 7, pj = row & 7;
                int h = (wi * 8 + pi + 4) & 63;
                int w = (wj * 8 + pj + 4) & 63;
                orow = (long)b * 4096 + h * 64 + w;
            } else {
                orow = row;
            }
            #pragma unroll
            for (int nt = 0; nt < 8; nt++) {
                int col = bn + wn * 64 + nt * 8 + 2 * tig;
                float v0 = acc[mt][nt][half * 2 + 0] + bias[col];
                float v1 = acc[mt][nt][half * 2 + 1] + bias[col + 1];
                if (EPI == 1) {
                    v0 = 0.5f * v0 * (1.f + erff(v0 * 0.70710678118654752f));
                    v1 = 0.5f * v1 * (1.f + erff(v1 * 0.70710678118654752f));
                }
                if (EPI == 2 || EPI == 3) {
                    float2 rr = *(const float2*)(R + orow * N + col);
                    v0 += rr.x; v1 += rr.y;
                }
                float2 o; o.x = v0; o.y = v1;
                *(float2*)(C + orow * N + col) = o;
            }
        }
    }
}

// ---------------------------------------------------------------------------
// Fused windowed attention, float4-vectorized smem traffic.
// Strides: Q/K/V rows = 36 floats (16B-aligned, conflict-free),
// P rows = 68 floats (store banks 4row+4c+l mod 32 all distinct).
// ---------------------------------------------------------------------------
__device__ __forceinline__ int bandf(int z) { return z < 56 ? 0 : (z < 60 ? 1 : 2); }

__global__ __launch_bounds__(256) void attn_kernel(
    const float* __restrict__ QKV, const float* __restrict__ bt,
    float* __restrict__ O)
{
    __shared__ float Qs[64][36];
    __shared__ float Ks[64][36];
    __shared__ float Vs[64][36];
    __shared__ float Ps[64][68];

    int win  = blockIdx.x;
    int head = blockIdx.y;
    int t = threadIdx.x;
    long base = (long)win * 64 * 768 + head * 32;

    #pragma unroll
    for (int i = 0; i < 2; i++) {
        int idx = t + i * 256;
        int row = idx >> 3, c4 = (idx & 7) * 4;
        const float* src = QKV + base + (long)row * 768 + c4;
        *(float4*)&Qs[row][c4] = *(const float4*)(src);
        *(float4*)&Ks[row][c4] = *(const float4*)(src + 256);
        *(float4*)&Vs[row][c4] = *(const float4*)(src + 512);
    }
    __syncthreads();

    int row = t >> 2, l = t & 3;
    float4 q4[8];
    #pragma unroll
    for (int k4 = 0; k4 < 8; k4++) q4[k4] = *(const float4*)&Qs[row][k4 * 4];

    int yi = row >> 3, xi = row & 7;
    int w_in_b = win & 63;
    int wwi = w_in_b >> 3, wwj = w_in_b & 7;
    bool edge = (wwi == 7) || (wwj == 7);
    int id_i = 0;
    if (edge) id_i = bandf(wwi * 8 + yi) * 3 + bandf(wwj * 8 + xi);

    const float scale = 0.17677669529663687f;
    float sreg[16];
    float mx = -1e30f;
    #pragma unroll
    for (int c = 0; c < 16; c++) {
        int col = c * 4 + l;
        float s = 0.f;
        #pragma unroll
        for (int k4 = 0; k4 < 8; k4++) {
            float4 kk = *(const float4*)&Ks[col][k4 * 4];
            s = fmaf(q4[k4].x, kk.x, s);
            s = fmaf(q4[k4].y, kk.y, s);
            s = fmaf(q4[k4].z, kk.z, s);
            s = fmaf(q4[k4].w, kk.w, s);
        }
        s *= scale;
        int yj = col >> 3, xj = col & 7;
        s += bt[((yi - yj + 7) * 15 + (xi - xj + 7)) * 8 + head];
        if (edge) {
            int id_j = bandf(wwi * 8 + yj) * 3 + bandf(wwj * 8 + xj);
            if (id_i != id_j) s -= 100.f;
        }
        sreg[c] = s;
        mx = fmaxf(mx, s);
    }
    mx = fmaxf(mx, __shfl_xor_sync(0xffffffffu, mx, 1));
    mx = fmaxf(mx, __shfl_xor_sync(0xffffffffu, mx, 2));

    float sum = 0.f;
    #pragma unroll
    for (int c = 0; c < 16; c++) {
        float p = __expf(sreg[c] - mx);
        sum += p;
        Ps[row][c * 4 + l] = p;
    }
    sum += __shfl_xor_sync(0xffffffffu, sum, 1);
    sum += __shfl_xor_sync(0xffffffffu, sum, 2);
    float rs = 1.f / sum;
    __syncthreads();

    float4 oa = {0.f, 0.f, 0.f, 0.f}, ob = {0.f, 0.f, 0.f, 0.f};
    #pragma unroll
    for (int cg = 0; cg < 16; cg++) {
        float4 p4 = *(const float4*)&Ps[row][cg * 4];
        #pragma unroll
        for (int j = 0; j < 4; j++) {
            int col = cg * 4 + j;
            float p = (j == 0) ? p4.x : (j == 1) ? p4.y : (j == 2) ? p4.z : p4.w;
            float4 va = *(const float4*)&Vs[col][l * 8];
            float4 vb = *(const float4*)&Vs[col][l * 8 + 4];
            oa.x = fmaf(p, va.x, oa.x); oa.y = fmaf(p, va.y, oa.y);
            oa.z = fmaf(p, va.z, oa.z); oa.w = fmaf(p, va.w, oa.w);
            ob.x = fmaf(p, vb.x, ob.x); ob.y = fmaf(p, vb.y, ob.y);
            ob.z = fmaf(p, vb.z, ob.z); ob.w = fmaf(p, vb.w, ob.w);
        }
    }
    float* op = O + ((long)win * 64 + row) * C_DIM + head * 32 + l * 8;
    float4 o0, o1;
    o0.x = oa.x*rs; o0.y = oa.y*rs; o0.z = oa.z*rs; o0.w = oa.w*rs;
    o1.x = ob.x*rs; o1.y = ob.y*rs; o1.z = ob.z*rs; o1.w = ob.w*rs;
    *(float4*)(op)     = o0;
    *(float4*)(op + 4) = o1;
}

// ---------------------------------------------------------------------------
// Launch
// ---------------------------------------------------------------------------
extern "C" void kernel_launch(void* const* d_in, const int* in_sizes, int n_in,
                              void* d_out, int out_size)
{
    const float* hidden = (const float*)d_in[0];
    const float* ln1_g  = (const float*)d_in[1];
    const float* ln1_b  = (const float*)d_in[2];
    const float* wq     = (const float*)d_in[3];
    const float* bq     = (const float*)d_in[4];
    const float* wk     = (const float*)d_in[5];
    const float* bk     = (const float*)d_in[6];
    const float* wv     = (const float*)d_in[7];
    const float* bv     = (const float*)d_in[8];
    const float* bt     = (const float*)d_in[9];
    const float* wo     = (const float*)d_in[10];
    const float* bo     = (const float*)d_in[11];
    const float* ln2_g  = (const float*)d_in[12];
    const float* ln2_b  = (const float*)d_in[13];
    const float* w1     = (const float*)d_in[14];
    const float* b1     = (const float*)d_in[15];
    const float* w2     = (const float*)d_in[16];
    const float* b2     = (const float*)d_in[17];
    float* out = (float*)d_out;

    float *p_xw, *p_qkv, *p_att, *p_hs, *p_y, *p_mid, *p_wqkv, *p_bqkv;
    cudaGetSymbolAddress((void**)&p_xw,   g_xw);
    cudaGetSymbolAddress((void**)&p_qkv,  g_qkv);
    cudaGetSymbolAddress((void**)&p_att,  g_att);
    cudaGetSymbolAddress((void**)&p_hs,   g_hs);
    cudaGetSymbolAddress((void**)&p_y,    g_y);
    cudaGetSymbolAddress((void**)&p_mid,  g_mid);
    cudaGetSymbolAddress((void**)&p_wqkv, g_wqkv);
    cudaGetSymbolAddress((void**)&p_bqkv, g_bqkv);

    cudaFuncSetAttribute(tf32gemm<0>, cudaFuncAttributeMaxDynamicSharedMemorySize, SMEM_SZ);
    cudaFuncSetAttribute(tf32gemm<1>, cudaFuncAttributeMaxDynamicSharedMemorySize, SMEM_SZ);
    cudaFuncSetAttribute(tf32gemm<2>, cudaFuncAttributeMaxDynamicSharedMemorySize, SMEM_SZ);
    cudaFuncSetAttribute(tf32gemm<3>, cudaFuncAttributeMaxDynamicSharedMemorySize, SMEM_SZ);

    dim3 blk(256);

    pack_qkv<<<768, blk>>>(wq, wk, wv, bq, bk, bv, p_wqkv, p_bqkv);
    ln_kernel<<<M_TOK / 8, blk>>>(hidden, ln1_g, ln1_b, p_xw, 1);
    tf32gemm<0><<<dim3(768 / BN, M_TOK / BM), blk, SMEM_SZ>>>(
        p_xw, p_wqkv, p_bqkv, nullptr, p_qkv, M_TOK, 768, C_DIM);
    attn_kernel<<<dim3(2048, 8), blk>>>(p_qkv, bt, p_att);
    tf32gemm<2><<<dim3(C_DIM / BN, M_TOK / BM), blk, SMEM_SZ>>>(
        p_att, wo, bo, hidden, p_hs, M_TOK, C_DIM, C_DIM);
    ln_kernel<<<M_TOK / 8, blk>>>(p_hs, ln2_g, ln2_b, p_y, 0);
    tf32gemm<1><<<dim3(DFF / BN, M_TOK / BM), blk, SMEM_SZ>>>(
        p_y, w1, b1, nullptr, p_mid, M_TOK, DFF, C_DIM);
    tf32gemm<3><<<dim3(C_DIM / BN, M_TOK / BM), blk, SMEM_SZ>>>(
        p_mid, w2, b2, p_hs, out, M_TOK, C_DIM, DFF);
}

// round 9
// speedup vs baseline: 1.1918x; 1.1504x over previous
#include <cuda_runtime.h>
#include <math.h>
#include <stdint.h>

// ---------------------------------------------------------------------------
// Problem constants: B=32, H=W=64, C=256, NH=8, hd=32, WS=8, SS=4, IM=4
// ---------------------------------------------------------------------------
#define M_TOK   131072
#define C_DIM   256
#define DFF     1024

// Scratch (device globals; no allocation at runtime)
__device__ float g_xw   [M_TOK * C_DIM];
__device__ float g_qkv  [M_TOK * 768];
__device__ float g_att  [M_TOK * C_DIM];
__device__ float g_hs   [M_TOK * C_DIM];
__device__ float g_y    [M_TOK * C_DIM];
__device__ float g_mid  [M_TOK * DFF];
__device__ float g_wqkv [C_DIM * 768];
__device__ float g_bqkv [768];

// ---------------------------------------------------------------------------
// cp.async helpers
// ---------------------------------------------------------------------------
__device__ __forceinline__ void cp_async16(void* smem, const void* gmem) {
    uint32_t s = (uint32_t)__cvta_generic_to_shared(smem);
    asm volatile("cp.async.cg.shared.global [%0], [%1], 16;\n" :: "r"(s), "l"(gmem));
}
__device__ __forceinline__ void cp_commit() {
    asm volatile("cp.async.commit_group;\n");
}
template<int N>
__device__ __forceinline__ void cp_wait() {
    asm volatile("cp.async.wait_group %0;\n" :: "n"(N));
}

__device__ __forceinline__ void mma_tf32(float d[4], const uint32_t a[4], const uint32_t b[2]) {
    asm volatile(
        "mma.sync.aligned.m16n8k8.row.col.f32.tf32.tf32.f32 "
        "{%0,%1,%2,%3}, {%4,%5,%6,%7}, {%8,%9}, {%0,%1,%2,%3};\n"
        : "+f"(d[0]), "+f"(d[1]), "+f"(d[2]), "+f"(d[3])
        : "r"(a[0]), "r"(a[1]), "r"(a[2]), "r"(a[3]), "r"(b[0]), "r"(b[1]));
}

// 3xTF32 split: hi = rna_tf32(x), lo = rna_tf32(x - hi)
__device__ __forceinline__ void split_tf32(float x, uint32_t& hi, uint32_t& lo) {
    uint32_t h;
    asm("cvt.rna.tf32.f32 %0, %1;" : "=r"(h) : "f"(x));
    float l = x - __uint_as_float(h);
    uint32_t l32;
    asm("cvt.rna.tf32.f32 %0, %1;" : "=r"(l32) : "f"(l));
    hi = h; lo = l32;
}

// ---------------------------------------------------------------------------
// Pack wq|wk|wv -> [256,768], bq|bk|bv -> [768]
// ---------------------------------------------------------------------------
__global__ __launch_bounds__(256) void pack_qkv(
    const float* __restrict__ wq, const float* __restrict__ wk,
    const float* __restrict__ wv, const float* __restrict__ bq,
    const float* __restrict__ bk, const float* __restrict__ bv,
    float* __restrict__ wdst, float* __restrict__ bdst)
{
    int idx = blockIdx.x * 256 + threadIdx.x;
    int k = idx / 768, n = idx % 768;
    float v = (n < 256) ? wq[k * 256 + n]
            : (n < 512) ? wk[k * 256 + n - 256]
                        : wv[k * 256 + n - 512];
    wdst[idx] = v;
    if (idx < 768)
        bdst[idx] = (idx < 256) ? bq[idx] : (idx < 512) ? bk[idx - 256] : bv[idx - 512];
}

// ---------------------------------------------------------------------------
// LayerNorm: warp-per-token, 8 tokens/block, float4 I/O.
// ---------------------------------------------------------------------------
__global__ __launch_bounds__(256) void ln_kernel(
    const float* __restrict__ x, const float* __restrict__ g,
    const float* __restrict__ bb, float* __restrict__ out, int gather)
{
    int warp = threadIdx.x >> 5, lane = threadIdx.x & 31;
    int r = blockIdx.x * 8 + warp;
    long src;
    if (gather) {
        int b  = r >> 12;
        int wi = (r >> 9) & 7, wj = (r >> 6) & 7;
        int pi = (r >> 3) & 7, pj = r & 7;
        int h = (wi * 8 + pi + 4) & 63;
        int w = (wj * 8 + pj + 4) & 63;
        src = (long)b * 4096 + h * 64 + w;
    } else {
        src = r;
    }
    const float4* xp = (const float4*)(x + src * C_DIM);
    float4 v0 = xp[lane * 2], v1 = xp[lane * 2 + 1];
    float s  = v0.x + v0.y + v0.z + v0.w + v1.x + v1.y + v1.z + v1.w;
    float s2 = v0.x*v0.x + v0.y*v0.y + v0.z*v0.z + v0.w*v0.w
             + v1.x*v1.x + v1.y*v1.y + v1.z*v1.z + v1.w*v1.w;
    #pragma unroll
    for (int o = 16; o > 0; o >>= 1) {
        s  += __shfl_xor_sync(0xffffffffu, s, o);
        s2 += __shfl_xor_sync(0xffffffffu, s2, o);
    }
    float mean = s * (1.f / 256.f);
    float var  = s2 * (1.f / 256.f) - mean * mean;
    float rstd = rsqrtf(var + 1e-5f);
    const float4* gp = (const float4*)(g  + lane * 8);
    const float4* bp = (const float4*)(bb + lane * 8);
    float4 g0 = gp[0], g1 = gp[1], b0 = bp[0], b1 = bp[1];
    float4 o0, o1;
    o0.x = (v0.x - mean) * rstd * g0.x + b0.x;
    o0.y = (v0.y - mean) * rstd * g0.y + b0.y;
    o0.z = (v0.z - mean) * rstd * g0.z + b0.z;
    o0.w = (v0.w - mean) * rstd * g0.w + b0.w;
    o1.x = (v1.x - mean) * rstd * g1.x + b1.x;
    o1.y = (v1.y - mean) * rstd * g1.y + b1.y;
    o1.z = (v1.z - mean) * rstd * g1.z + b1.z;
    o1.w = (v1.w - mean) * rstd * g1.w + b1.w;
    float4* op = (float4*)(out + (long)r * C_DIM + lane * 8);
    op[0] = o0; op[1] = o1;
}

// ---------------------------------------------------------------------------
// TF32 tensor-core GEMM (unchanged)
// ---------------------------------------------------------------------------
#define NSTG 3
#define BM   128
#define BN   256
#define ASTR 20
#define BSTR 264
#define A_STAGE (BM * ASTR)
#define B_STAGE (16 * BSTR)
#define SMEM_SZ ((NSTG * (A_STAGE + B_STAGE)) * 4)

template<int EPI>
__global__ __launch_bounds__(256, 1) void tf32gemm(
    const float* __restrict__ A, const float* __restrict__ B,
    const float* __restrict__ bias, const float* __restrict__ R,
    float* __restrict__ C, int M, int N, int K)
{
    extern __shared__ float sm[];
    float* Asm = sm;
    float* Bsm = sm + NSTG * A_STAGE;

    int tid  = threadIdx.x;
    int lane = tid & 31, warp = tid >> 5;
    int wm = warp >> 2, wn = warp & 3;
    int bm = blockIdx.y * BM, bn = blockIdx.x * BN;
    int gid = lane >> 2, tig = lane & 3;

    float acc[4][8][4];
    #pragma unroll
    for (int mt = 0; mt < 4; mt++)
        #pragma unroll
        for (int nt = 0; nt < 8; nt++)
            #pragma unroll
            for (int i = 0; i < 4; i++) acc[mt][nt][i] = 0.f;

    int aR[2], aC[2], bR[4], bC[4];
    #pragma unroll
    for (int i = 0; i < 2; i++) {
        int s = tid + i * 256;
        aR[i] = s >> 2;  aC[i] = (s & 3) * 4;
    }
    #pragma unroll
    for (int i = 0; i < 4; i++) {
        int s = tid + i * 256;
        bR[i] = s >> 6;  bC[i] = (s & 63) * 4;
    }

    int KT = K >> 4;

    #pragma unroll
    for (int s = 0; s < NSTG - 1; s++) {
        int kb = s << 4;
        float* as = Asm + s * A_STAGE;
        float* bs = Bsm + s * B_STAGE;
        #pragma unroll
        for (int i = 0; i < 2; i++)
            cp_async16(&as[aR[i] * ASTR + aC[i]], A + (long)(bm + aR[i]) * K + kb + aC[i]);
        #pragma unroll
        for (int i = 0; i < 4; i++)
            cp_async16(&bs[bR[i] * BSTR + bC[i]], B + (long)(kb + bR[i]) * N + bn + bC[i]);
        cp_commit();
    }

    for (int kt = 0; kt < KT; kt++) {
        if (kt + NSTG - 1 < KT) cp_wait<NSTG - 2>(); else cp_wait<0>();
        __syncthreads();
        int stg = kt % NSTG;
        const float* as = Asm + stg * A_STAGE;
        const float* bs = Bsm + stg * B_STAGE;
        #pragma unroll
        for (int ks = 0; ks < 2; ks++) {
            uint32_t af[4][4], bf[8][2];
            #pragma unroll
            for (int mt = 0; mt < 4; mt++) {
                int r0 = wm * 64 + mt * 16 + gid;
                int c0 = ks * 8 + tig;
                af[mt][0] = __float_as_uint(as[r0 * ASTR + c0]);
                af[mt][1] = __float_as_uint(as[(r0 + 8) * ASTR + c0]);
                af[mt][2] = __float_as_uint(as[r0 * ASTR + c0 + 4]);
                af[mt][3] = __float_as_uint(as[(r0 + 8) * ASTR + c0 + 4]);
            }
            #pragma unroll
            for (int nt = 0; nt < 8; nt++) {
                int rr = ks * 8 + tig;
                int cc = wn * 64 + nt * 8 + gid;
                bf[nt][0] = __float_as_uint(bs[rr * BSTR + cc]);
                bf[nt][1] = __float_as_uint(bs[(rr + 4) * BSTR + cc]);
            }
            #pragma unroll
            for (int mt = 0; mt < 4; mt++)
                #pragma unroll
                for (int nt = 0; nt < 8; nt++)
                    mma_tf32(acc[mt][nt], af[mt], bf[nt]);
        }
        if (kt + NSTG - 1 < KT) {
            int kn = kt + NSTG - 1;
            int kb = kn << 4;
            int ds = kn % NSTG;
            float* asn = Asm + ds * A_STAGE;
            float* bsn = Bsm + ds * B_STAGE;
            #pragma unroll
            for (int i = 0; i < 2; i++)
                cp_async16(&asn[aR[i] * ASTR + aC[i]], A + (long)(bm + aR[i]) * K + kb + aC[i]);
            #pragma unroll
            for (int i = 0; i < 4; i++)
                cp_async16(&bsn[bR[i] * BSTR + bC[i]], B + (long)(kb + bR[i]) * N + bn + bC[i]);
            cp_commit();
        }
    }

    #pragma unroll
    for (int mt = 0; mt < 4; mt++) {
        #pragma unroll
        for (int half = 0; half < 2; half++) {
            int row = bm + wm * 64 + mt * 16 + half * 8 + gid;
            long orow;
            if (EPI == 2) {
                int b  = row >> 12;
                int wi = (row >> 9) & 7, wj = (row >> 6) & 7;
                int pi = (row >> 3) & 7, pj = row & 7;
                int h = (wi * 8 + pi + 4) & 63;
                int w = (wj * 8 + pj + 4) & 63;
                orow = (long)b * 4096 + h * 64 + w;
            } else {
                orow = row;
            }
            #pragma unroll
            for (int nt = 0; nt < 8; nt++) {
                int col = bn + wn * 64 + nt * 8 + 2 * tig;
                float v0 = acc[mt][nt][half * 2 + 0] + bias[col];
                float v1 = acc[mt][nt][half * 2 + 1] + bias[col + 1];
                if (EPI == 1) {
                    v0 = 0.5f * v0 * (1.f + erff(v0 * 0.70710678118654752f));
                    v1 = 0.5f * v1 * (1.f + erff(v1 * 0.70710678118654752f));
                }
                if (EPI == 2 || EPI == 3) {
                    float2 rr = *(const float2*)(R + orow * N + col);
                    v0 += rr.x; v1 += rr.y;
                }
                float2 o; o.x = v0; o.y = v1;
                *(float2*)(C + orow * N + col) = o;
            }
        }
    }
}

// ---------------------------------------------------------------------------
// Tensor-core windowed attention with 3xTF32 (fp32-equivalent precision).
// One block = one (window, head), 128 threads / 4 warps.
// Conflict-free strides: Q/K 36, V 40, P 68.
// ---------------------------------------------------------------------------
#define QSTR 36
#define VSTR 40
#define PSTR 68

__device__ __forceinline__ int bandf(int z) { return z < 56 ? 0 : (z < 60 ? 1 : 2); }

__global__ __launch_bounds__(128) void attn_kernel(
    const float* __restrict__ QKV, const float* __restrict__ bt,
    float* __restrict__ O)
{
    __shared__ float Qs[64 * QSTR];
    __shared__ float Ks[64 * QSTR];
    __shared__ float Vs[64 * VSTR];
    __shared__ float Ps[64 * PSTR];
    __shared__ float btS[228];

    int win  = blockIdx.x;
    int head = blockIdx.y;
    int t = threadIdx.x;
    int warp = t >> 5, lane = t & 31;
    int gid = lane >> 2, tig = lane & 3;
    long base = (long)win * 64 * 768 + head * 32;

    // FIX (R8 bug): block has 128 threads, table has 225 entries — loop.
    for (int i = t; i < 225; i += 128) btS[i] = bt[i * 8 + head];

    const float scale = 0.17677669529663687f;   // 32^-0.5
    #pragma unroll
    for (int i = 0; i < 4; i++) {
        int idx = t + i * 128;                  // 512 float4 slots
        int row = idx >> 3, c4 = (idx & 7) * 4;
        const float* src = QKV + base + (long)row * 768 + c4;
        float4 q = *(const float4*)(src);
        q.x *= scale; q.y *= scale; q.z *= scale; q.w *= scale;
        *(float4*)&Qs[row * QSTR + c4] = q;
        *(float4*)&Ks[row * QSTR + c4] = *(const float4*)(src + 256);
        *(float4*)&Vs[row * VSTR + c4] = *(const float4*)(src + 512);
    }
    __syncthreads();

    // ---- S = Q@K^T (3xTF32): warp covers key-cols [warp*16, warp*16+16) ----
    float sc[4][2][4];
    #pragma unroll
    for (int mt = 0; mt < 4; mt++)
        #pragma unroll
        for (int nt = 0; nt < 2; nt++)
            #pragma unroll
            for (int i = 0; i < 4; i++) sc[mt][nt][i] = 0.f;

    #pragma unroll
    for (int kt = 0; kt < 4; kt++) {
        uint32_t ah[4][4], al[4][4], bh[2][2], bl[2][2];
        #pragma unroll
        for (int mt = 0; mt < 4; mt++) {
            int r0 = mt * 16 + gid;
            int c0 = kt * 8 + tig;
            split_tf32(Qs[r0 * QSTR + c0],           ah[mt][0], al[mt][0]);
            split_tf32(Qs[(r0 + 8) * QSTR + c0],     ah[mt][1], al[mt][1]);
            split_tf32(Qs[r0 * QSTR + c0 + 4],       ah[mt][2], al[mt][2]);
            split_tf32(Qs[(r0 + 8) * QSTR + c0 + 4], ah[mt][3], al[mt][3]);
        }
        #pragma unroll
        for (int nt = 0; nt < 2; nt++) {
            int kr = warp * 16 + nt * 8 + gid;
            int kc = kt * 8 + tig;
            split_tf32(Ks[kr * QSTR + kc],     bh[nt][0], bl[nt][0]);
            split_tf32(Ks[kr * QSTR + kc + 4], bh[nt][1], bl[nt][1]);
        }
        #pragma unroll
        for (int mt = 0; mt < 4; mt++)
            #pragma unroll
            for (int nt = 0; nt < 2; nt++) {
                mma_tf32(sc[mt][nt], al[mt], bh[nt]);   // small terms first
                mma_tf32(sc[mt][nt], ah[mt], bl[nt]);
                mma_tf32(sc[mt][nt], ah[mt], bh[nt]);
            }
    }

    // ---- bias + shift mask, store S to Ps ----
    int w_in_b = win & 63;
    int wwi = w_in_b >> 3, wwj = w_in_b & 7;
    bool edge = (wwi == 7) || (wwj == 7);
    #pragma unroll
    for (int mt = 0; mt < 4; mt++) {
        #pragma unroll
        for (int half = 0; half < 2; half++) {
            int r = mt * 16 + half * 8 + gid;
            int yi = r >> 3, xi = r & 7;
            int id_i = edge ? bandf(wwi * 8 + yi) * 3 + bandf(wwj * 8 + xi) : 0;
            #pragma unroll
            for (int nt = 0; nt < 2; nt++) {
                int c0 = warp * 16 + nt * 8 + 2 * tig;
                float v0 = sc[mt][nt][half * 2 + 0];
                float v1 = sc[mt][nt][half * 2 + 1];
                #pragma unroll
                for (int j = 0; j < 2; j++) {
                    int c = c0 + j;
                    int yj = c >> 3, xj = c & 7;
                    float add = btS[(yi - yj + 7) * 15 + (xi - xj + 7)];
                    if (edge) {
                        int id_j = bandf(wwi * 8 + yj) * 3 + bandf(wwj * 8 + xj);
                        if (id_i != id_j) add -= 100.f;
                    }
                    if (j == 0) v0 += add; else v1 += add;
                }
                float2 st; st.x = v0; st.y = v1;
                *(float2*)&Ps[r * PSTR + c0] = st;
            }
        }
    }
    __syncthreads();

    // ---- softmax: thread handles half a row ----
    {
        int row = t >> 1;
        int c0 = (t & 1) * 32;
        float4 e[8];
        float mx = -1e30f;
        #pragma unroll
        for (int i = 0; i < 8; i++) {
            e[i] = *(const float4*)&Ps[row * PSTR + c0 + i * 4];
            mx = fmaxf(mx, fmaxf(fmaxf(e[i].x, e[i].y), fmaxf(e[i].z, e[i].w)));
        }
        mx = fmaxf(mx, __shfl_xor_sync(0xffffffffu, mx, 1));
        float sum = 0.f;
        #pragma unroll
        for (int i = 0; i < 8; i++) {
            e[i].x = __expf(e[i].x - mx); e[i].y = __expf(e[i].y - mx);
            e[i].z = __expf(e[i].z - mx); e[i].w = __expf(e[i].w - mx);
            sum += e[i].x + e[i].y + e[i].z + e[i].w;
        }
        sum += __shfl_xor_sync(0xffffffffu, sum, 1);
        float rs = 1.f / sum;
        #pragma unroll
        for (int i = 0; i < 8; i++) {
            e[i].x *= rs; e[i].y *= rs; e[i].z *= rs; e[i].w *= rs;
            *(float4*)&Ps[row * PSTR + c0 + i * 4] = e[i];
        }
    }
    __syncthreads();

    // ---- O = P@V (3xTF32): warp covers query-rows [warp*16, warp*16+16) ----
    float oc[4][4];
    #pragma unroll
    for (int nt = 0; nt < 4; nt++)
        #pragma unroll
        for (int i = 0; i < 4; i++) oc[nt][i] = 0.f;

    #pragma unroll
    for (int kt = 0; kt < 8; kt++) {
        uint32_t ah[4], al[4], bh[4][2], bl[4][2];
        int r0 = warp * 16 + gid;
        int c0 = kt * 8 + tig;
        split_tf32(Ps[r0 * PSTR + c0],           ah[0], al[0]);
        split_tf32(Ps[(r0 + 8) * PSTR + c0],     ah[1], al[1]);
        split_tf32(Ps[r0 * PSTR + c0 + 4],       ah[2], al[2]);
        split_tf32(Ps[(r0 + 8) * PSTR + c0 + 4], ah[3], al[3]);
        #pragma unroll
        for (int nt = 0; nt < 4; nt++) {
            int vr = kt * 8 + tig;
            int vc = nt * 8 + gid;
            split_tf32(Vs[vr * VSTR + vc],       bh[nt][0], bl[nt][0]);
            split_tf32(Vs[(vr + 4) * VSTR + vc], bh[nt][1], bl[nt][1]);
        }
        #pragma unroll
        for (int nt = 0; nt < 4; nt++) {
            mma_tf32(oc[nt], al, bh[nt]);
            mma_tf32(oc[nt], ah, bl[nt]);
            mma_tf32(oc[nt], ah, bh[nt]);
        }
    }

    // ---- write O ----
    long obase = ((long)win * 64) * C_DIM + head * 32;
    #pragma unroll
    for (int half = 0; half < 2; half++) {
        int row = warp * 16 + half * 8 + gid;
        #pragma unroll
        for (int nt = 0; nt < 4; nt++) {
            int col = nt * 8 + 2 * tig;
            float2 o;
            o.x = oc[nt][half * 2 + 0];
            o.y = oc[nt][half * 2 + 1];
            *(float2*)(O + obase + (long)row * C_DIM + col) = o;
        }
    }
}

// ---------------------------------------------------------------------------
// Launch
// ---------------------------------------------------------------------------
extern "C" void kernel_launch(void* const* d_in, const int* in_sizes, int n_in,
                              void* d_out, int out_size)
{
    const float* hidden = (const float*)d_in[0];
    const float* ln1_g  = (const float*)d_in[1];
    const float* ln1_b  = (const float*)d_in[2];
    const float* wq     = (const float*)d_in[3];
    const float* bq     = (const float*)d_in[4];
    const float* wk     = (const float*)d_in[5];
    const float* bk     = (const float*)d_in[6];
    const float* wv     = (const float*)d_in[7];
    const float* bv     = (const float*)d_in[8];
    const float* bt     = (const float*)d_in[9];
    const float* wo     = (const float*)d_in[10];
    const float* bo     = (const float*)d_in[11];
    const float* ln2_g  = (const float*)d_in[12];
    const float* ln2_b  = (const float*)d_in[13];
    const float* w1     = (const float*)d_in[14];
    const float* b1     = (const float*)d_in[15];
    const float* w2     = (const float*)d_in[16];
    const float* b2     = (const float*)d_in[17];
    float* out = (float*)d_out;

    float *p_xw, *p_qkv, *p_att, *p_hs, *p_y, *p_mid, *p_wqkv, *p_bqkv;
    cudaGetSymbolAddress((void**)&p_xw,   g_xw);
    cudaGetSymbolAddress((void**)&p_qkv,  g_qkv);
    cudaGetSymbolAddress((void**)&p_att,  g_att);
    cudaGetSymbolAddress((void**)&p_hs,   g_hs);
    cudaGetSymbolAddress((void**)&p_y,    g_y);
    cudaGetSymbolAddress((void**)&p_mid,  g_mid);
    cudaGetSymbolAddress((void**)&p_wqkv, g_wqkv);
    cudaGetSymbolAddress((void**)&p_bqkv, g_bqkv);

    cudaFuncSetAttribute(tf32gemm<0>, cudaFuncAttributeMaxDynamicSharedMemorySize, SMEM_SZ);
    cudaFuncSetAttribute(tf32gemm<1>, cudaFuncAttributeMaxDynamicSharedMemorySize, SMEM_SZ);
    cudaFuncSetAttribute(tf32gemm<2>, cudaFuncAttributeMaxDynamicSharedMemorySize, SMEM_SZ);
    cudaFuncSetAttribute(tf32gemm<3>, cudaFuncAttributeMaxDynamicSharedMemorySize, SMEM_SZ);

    dim3 blk(256);

    pack_qkv<<<768, blk>>>(wq, wk, wv, bq, bk, bv, p_wqkv, p_bqkv);
    ln_kernel<<<M_TOK / 8, blk>>>(hidden, ln1_g, ln1_b, p_xw, 1);
    tf32gemm<0><<<dim3(768 / BN, M_TOK / BM), blk, SMEM_SZ>>>(
        p_xw, p_wqkv, p_bqkv, nullptr, p_qkv, M_TOK, 768, C_DIM);
    attn_kernel<<<dim3(2048, 8), dim3(128)>>>(p_qkv, bt, p_att);
    tf32gemm<2><<<dim3(C_DIM / BN, M_TOK / BM), blk, SMEM_SZ>>>(
        p_att, wo, bo, hidden, p_hs, M_TOK, C_DIM, C_DIM);
    ln_kernel<<<M_TOK / 8, blk>>>(p_hs, ln2_g, ln2_b, p_y, 0);
    tf32gemm<1><<<dim3(DFF / BN, M_TOK / BM), blk, SMEM_SZ>>>(
        p_y, w1, b1, nullptr, p_mid, M_TOK, DFF, C_DIM);
    tf32gemm<3><<<dim3(C_DIM / BN, M_TOK / BM), blk, SMEM_SZ>>>(
        p_mid, w2, b2, p_hs, out, M_TOK, C_DIM, DFF);
}

// round 10
// speedup vs baseline: 1.2648x; 1.0613x over previous
#include <cuda_runtime.h>
#include <math.h>
#include <stdint.h>

// ---------------------------------------------------------------------------
// Problem constants: B=32, H=W=64, C=256, NH=8, hd=32, WS=8, SS=4, IM=4
// ---------------------------------------------------------------------------
#define M_TOK   131072
#define C_DIM   256
#define DFF     1024

// Scratch (device globals; no allocation at runtime)
__device__ float g_xw   [M_TOK * C_DIM];
__device__ float g_qkv  [M_TOK * 768];
__device__ float g_att  [M_TOK * C_DIM];
__device__ float g_hs   [M_TOK * C_DIM];
__device__ float g_y    [M_TOK * C_DIM];
__device__ float g_mid  [M_TOK * DFF];
__device__ float g_wqkv [C_DIM * 768];
__device__ float g_bqkv [768];

// ---------------------------------------------------------------------------
// cp.async helpers
// ---------------------------------------------------------------------------
__device__ __forceinline__ void cp_async16(void* smem, const void* gmem) {
    uint32_t s = (uint32_t)__cvta_generic_to_shared(smem);
    asm volatile("cp.async.cg.shared.global [%0], [%1], 16;\n" :: "r"(s), "l"(gmem));
}
__device__ __forceinline__ void cp_commit() {
    asm volatile("cp.async.commit_group;\n");
}
template<int N>
__device__ __forceinline__ void cp_wait() {
    asm volatile("cp.async.wait_group %0;\n" :: "n"(N));
}

__device__ __forceinline__ void mma_tf32(float d[4], const uint32_t a[4], const uint32_t b[2]) {
    asm volatile(
        "mma.sync.aligned.m16n8k8.row.col.f32.tf32.tf32.f32 "
        "{%0,%1,%2,%3}, {%4,%5,%6,%7}, {%8,%9}, {%0,%1,%2,%3};\n"
        : "+f"(d[0]), "+f"(d[1]), "+f"(d[2]), "+f"(d[3])
        : "r"(a[0]), "r"(a[1]), "r"(a[2]), "r"(a[3]), "r"(b[0]), "r"(b[1]));
}

// ---------------------------------------------------------------------------
// Pack wq|wk|wv -> [256,768], bq|bk|bv -> [768]
// ---------------------------------------------------------------------------
__global__ __launch_bounds__(256) void pack_qkv(
    const float* __restrict__ wq, const float* __restrict__ wk,
    const float* __restrict__ wv, const float* __restrict__ bq,
    const float* __restrict__ bk, const float* __restrict__ bv,
    float* __restrict__ wdst, float* __restrict__ bdst)
{
    int idx = blockIdx.x * 256 + threadIdx.x;
    int k = idx / 768, n = idx % 768;
    float v = (n < 256) ? wq[k * 256 + n]
            : (n < 512) ? wk[k * 256 + n - 256]
                        : wv[k * 256 + n - 512];
    wdst[idx] = v;
    if (idx < 768)
        bdst[idx] = (idx < 256) ? bq[idx] : (idx < 512) ? bk[idx - 256] : bv[idx - 512];
}

// ---------------------------------------------------------------------------
// LayerNorm: warp-per-token, 8 tokens/block, float4 I/O. (LN1 only now)
// ---------------------------------------------------------------------------
__global__ __launch_bounds__(256) void ln_kernel(
    const float* __restrict__ x, const float* __restrict__ g,
    const float* __restrict__ bb, float* __restrict__ out, int gather)
{
    int warp = threadIdx.x >> 5, lane = threadIdx.x & 31;
    int r = blockIdx.x * 8 + warp;
    long src;
    if (gather) {
        int b  = r >> 12;
        int wi = (r >> 9) & 7, wj = (r >> 6) & 7;
        int pi = (r >> 3) & 7, pj = r & 7;
        int h = (wi * 8 + pi + 4) & 63;
        int w = (wj * 8 + pj + 4) & 63;
        src = (long)b * 4096 + h * 64 + w;
    } else {
        src = r;
    }
    const float4* xp = (const float4*)(x + src * C_DIM);
    float4 v0 = xp[lane * 2], v1 = xp[lane * 2 + 1];
    float s  = v0.x + v0.y + v0.z + v0.w + v1.x + v1.y + v1.z + v1.w;
    float s2 = v0.x*v0.x + v0.y*v0.y + v0.z*v0.z + v0.w*v0.w
             + v1.x*v1.x + v1.y*v1.y + v1.z*v1.z + v1.w*v1.w;
    #pragma unroll
    for (int o = 16; o > 0; o >>= 1) {
        s  += __shfl_xor_sync(0xffffffffu, s, o);
        s2 += __shfl_xor_sync(0xffffffffu, s2, o);
    }
    float mean = s * (1.f / 256.f);
    float var  = s2 * (1.f / 256.f) - mean * mean;
    float rstd = rsqrtf(var + 1e-5f);
    const float4* gp = (const float4*)(g  + lane * 8);
    const float4* bp = (const float4*)(bb + lane * 8);
    float4 g0 = gp[0], g1 = gp[1], b0 = bp[0], b1 = bp[1];
    float4 o0, o1;
    o0.x = (v0.x - mean) * rstd * g0.x + b0.x;
    o0.y = (v0.y - mean) * rstd * g0.y + b0.y;
    o0.z = (v0.z - mean) * rstd * g0.z + b0.z;
    o0.w = (v0.w - mean) * rstd * g0.w + b0.w;
    o1.x = (v1.x - mean) * rstd * g1.x + b1.x;
    o1.y = (v1.y - mean) * rstd * g1.y + b1.y;
    o1.z = (v1.z - mean) * rstd * g1.z + b1.z;
    o1.w = (v1.w - mean) * rstd * g1.w + b1.w;
    float4* op = (float4*)(out + (long)r * C_DIM + lane * 8);
    op[0] = o0; op[1] = o1;
}

// ---------------------------------------------------------------------------
// TF32 tensor-core GEMM: C = epi(A[MxK] @ B[KxN] + bias)
// EPI 0: plain. 1: GELU. 2: scatter+residual -> hs AND fused LN2 -> Y.
// EPI 3: residual.
// EPI==2 requires BN == N (block owns complete rows).
// ---------------------------------------------------------------------------
#define NSTG 3
#define BM   128
#define BN   256
#define ASTR 20
#define BSTR 264
#define A_STAGE (BM * ASTR)
#define B_STAGE (16 * BSTR)
#define SMEM_SZ ((NSTG * (A_STAGE + B_STAGE)) * 4)

template<int EPI>
__global__ __launch_bounds__(256, 1) void tf32gemm(
    const float* __restrict__ A, const float* __restrict__ B,
    const float* __restrict__ bias, const float* __restrict__ R,
    float* __restrict__ C, int M, int N, int K,
    const float* __restrict__ G2, const float* __restrict__ B2,
    float* __restrict__ Y)
{
    extern __shared__ float sm[];
    float* Asm = sm;
    float* Bsm = sm + NSTG * A_STAGE;

    int tid  = threadIdx.x;
    int lane = tid & 31, warp = tid >> 5;
    int wm = warp >> 2, wn = warp & 3;
    int bm = blockIdx.y * BM, bn = blockIdx.x * BN;
    int gid = lane >> 2, tig = lane & 3;

    float acc[4][8][4];
    #pragma unroll
    for (int mt = 0; mt < 4; mt++)
        #pragma unroll
        for (int nt = 0; nt < 8; nt++)
            #pragma unroll
            for (int i = 0; i < 4; i++) acc[mt][nt][i] = 0.f;

    int aR[2], aC[2], bR[4], bC[4];
    #pragma unroll
    for (int i = 0; i < 2; i++) {
        int s = tid + i * 256;
        aR[i] = s >> 2;  aC[i] = (s & 3) * 4;
    }
    #pragma unroll
    for (int i = 0; i < 4; i++) {
        int s = tid + i * 256;
        bR[i] = s >> 6;  bC[i] = (s & 63) * 4;
    }

    int KT = K >> 4;

    #pragma unroll
    for (int s = 0; s < NSTG - 1; s++) {
        int kb = s << 4;
        float* as = Asm + s * A_STAGE;
        float* bs = Bsm + s * B_STAGE;
        #pragma unroll
        for (int i = 0; i < 2; i++)
            cp_async16(&as[aR[i] * ASTR + aC[i]], A + (long)(bm + aR[i]) * K + kb + aC[i]);
        #pragma unroll
        for (int i = 0; i < 4; i++)
            cp_async16(&bs[bR[i] * BSTR + bC[i]], B + (long)(kb + bR[i]) * N + bn + bC[i]);
        cp_commit();
    }

    for (int kt = 0; kt < KT; kt++) {
        if (kt + NSTG - 1 < KT) cp_wait<NSTG - 2>(); else cp_wait<0>();
        __syncthreads();
        int stg = kt % NSTG;
        const float* as = Asm + stg * A_STAGE;
        const float* bs = Bsm + stg * B_STAGE;
        #pragma unroll
        for (int ks = 0; ks < 2; ks++) {
            uint32_t af[4][4], bf[8][2];
            #pragma unroll
            for (int mt = 0; mt < 4; mt++) {
                int r0 = wm * 64 + mt * 16 + gid;
                int c0 = ks * 8 + tig;
                af[mt][0] = __float_as_uint(as[r0 * ASTR + c0]);
                af[mt][1] = __float_as_uint(as[(r0 + 8) * ASTR + c0]);
                af[mt][2] = __float_as_uint(as[r0 * ASTR + c0 + 4]);
                af[mt][3] = __float_as_uint(as[(r0 + 8) * ASTR + c0 + 4]);
            }
            #pragma unroll
            for (int nt = 0; nt < 8; nt++) {
                int rr = ks * 8 + tig;
                int cc = wn * 64 + nt * 8 + gid;
                bf[nt][0] = __float_as_uint(bs[rr * BSTR + cc]);
                bf[nt][1] = __float_as_uint(bs[(rr + 4) * BSTR + cc]);
            }
            #pragma unroll
            for (int mt = 0; mt < 4; mt++)
                #pragma unroll
                for (int nt = 0; nt < 8; nt++)
                    mma_tf32(acc[mt][nt], af[mt], bf[nt]);
        }
        if (kt + NSTG - 1 < KT) {
            int kn = kt + NSTG - 1;
            int kb = kn << 4;
            int ds = kn % NSTG;
            float* asn = Asm + ds * A_STAGE;
            float* bsn = Bsm + ds * B_STAGE;
            #pragma unroll
            for (int i = 0; i < 2; i++)
                cp_async16(&asn[aR[i] * ASTR + aC[i]], A + (long)(bm + aR[i]) * K + kb + aC[i]);
            #pragma unroll
            for (int i = 0; i < 4; i++)
                cp_async16(&bsn[bR[i] * BSTR + bC[i]], B + (long)(kb + bR[i]) * N + bn + bC[i]);
            cp_commit();
        }
    }

    if (EPI == 2) {
        // ---- fused: hs = GEMM + bias + residual (scattered), y = LN(hs) ----
        __syncthreads();                 // before reusing smem for reduction
        float* red = sm;                 // 128 rows x (4 warps x {sum,sq}) = 4KB
        long orows[4][2];
        float rsum[4][2], rsq[4][2];
        #pragma unroll
        for (int mt = 0; mt < 4; mt++) {
            #pragma unroll
            for (int half = 0; half < 2; half++) {
                int row = bm + wm * 64 + mt * 16 + half * 8 + gid;
                int b  = row >> 12;
                int wi = (row >> 9) & 7, wj = (row >> 6) & 7;
                int pi = (row >> 3) & 7, pj = row & 7;
                int h = (wi * 8 + pi + 4) & 63;
                int w = (wj * 8 + pj + 4) & 63;
                long orow = (long)b * 4096 + h * 64 + w;
                orows[mt][half] = orow;
                float s = 0.f, q = 0.f;
                #pragma unroll
                for (int nt = 0; nt < 8; nt++) {
                    int col = bn + wn * 64 + nt * 8 + 2 * tig;
                    float v0 = acc[mt][nt][half * 2 + 0] + bias[col];
                    float v1 = acc[mt][nt][half * 2 + 1] + bias[col + 1];
                    float2 rr = *(const float2*)(R + orow * N + col);
                    v0 += rr.x; v1 += rr.y;
                    acc[mt][nt][half * 2 + 0] = v0;
                    acc[mt][nt][half * 2 + 1] = v1;
                    s += v0 + v1;
                    q += v0 * v0 + v1 * v1;
                    float2 o; o.x = v0; o.y = v1;
                    *(float2*)(C + orow * N + col) = o;
                }
                rsum[mt][half] = s; rsq[mt][half] = q;
            }
        }
        #pragma unroll
        for (int mt = 0; mt < 4; mt++) {
            #pragma unroll
            for (int half = 0; half < 2; half++) {
                float s = rsum[mt][half], q = rsq[mt][half];
                s += __shfl_xor_sync(0xffffffffu, s, 1);
                q += __shfl_xor_sync(0xffffffffu, q, 1);
                s += __shfl_xor_sync(0xffffffffu, s, 2);
                q += __shfl_xor_sync(0xffffffffu, q, 2);
                if (tig == 0) {
                    int lr = wm * 64 + mt * 16 + half * 8 + gid;
                    red[lr * 8 + wn * 2]     = s;
                    red[lr * 8 + wn * 2 + 1] = q;
                }
            }
        }
        __syncthreads();
        #pragma unroll
        for (int mt = 0; mt < 4; mt++) {
            #pragma unroll
            for (int half = 0; half < 2; half++) {
                int lr = wm * 64 + mt * 16 + half * 8 + gid;
                float s = red[lr*8+0] + red[lr*8+2] + red[lr*8+4] + red[lr*8+6];
                float q = red[lr*8+1] + red[lr*8+3] + red[lr*8+5] + red[lr*8+7];
                float mean = s * (1.f / 256.f);
                float var  = q * (1.f / 256.f) - mean * mean;
                float rstd = rsqrtf(var + 1e-5f);
                long orow = orows[mt][half];
                #pragma unroll
                for (int nt = 0; nt < 8; nt++) {
                    int col = bn + wn * 64 + nt * 8 + 2 * tig;
                    float v0 = acc[mt][nt][half * 2 + 0];
                    float v1 = acc[mt][nt][half * 2 + 1];
                    float2 o;
                    o.x = (v0 - mean) * rstd * G2[col]     + B2[col];
                    o.y = (v1 - mean) * rstd * G2[col + 1] + B2[col + 1];
                    *(float2*)(Y + orow * N + col) = o;
                }
            }
        }
        return;
    }

    // ---- standard epilogues (EPI 0, 1, 3) ----
    #pragma unroll
    for (int mt = 0; mt < 4; mt++) {
        #pragma unroll
        for (int half = 0; half < 2; half++) {
            int row = bm + wm * 64 + mt * 16 + half * 8 + gid;
            long orow = row;
            #pragma unroll
            for (int nt = 0; nt < 8; nt++) {
                int col = bn + wn * 64 + nt * 8 + 2 * tig;
                float v0 = acc[mt][nt][half * 2 + 0] + bias[col];
                float v1 = acc[mt][nt][half * 2 + 1] + bias[col + 1];
                if (EPI == 1) {
                    v0 = 0.5f * v0 * (1.f + erff(v0 * 0.70710678118654752f));
                    v1 = 0.5f * v1 * (1.f + erff(v1 * 0.70710678118654752f));
                }
                if (EPI == 3) {
                    float2 rr = *(const float2*)(R + orow * N + col);
                    v0 += rr.x; v1 += rr.y;
                }
                float2 o; o.x = v0; o.y = v1;
                *(float2*)(C + orow * N + col) = o;
            }
        }
    }
}

// ---------------------------------------------------------------------------
// Tensor-core windowed attention, 1xTF32 (direct fp32-bit fragments).
// One block = one (window, head), 128 threads / 4 warps.
// Conflict-free strides: Q/K 36, V 40, P 68.
// ---------------------------------------------------------------------------
#define QSTR 36
#define VSTR 40
#define PSTR 68

__device__ __forceinline__ int bandf(int z) { return z < 56 ? 0 : (z < 60 ? 1 : 2); }

__global__ __launch_bounds__(128) void attn_kernel(
    const float* __restrict__ QKV, const float* __restrict__ bt,
    float* __restrict__ O)
{
    __shared__ float Qs[64 * QSTR];
    __shared__ float Ks[64 * QSTR];
    __shared__ float Vs[64 * VSTR];
    __shared__ float Ps[64 * PSTR];
    __shared__ float btS[228];

    int win  = blockIdx.x;
    int head = blockIdx.y;
    int t = threadIdx.x;
    int warp = t >> 5, lane = t & 31;
    int gid = lane >> 2, tig = lane & 3;
    long base = (long)win * 64 * 768 + head * 32;

    for (int i = t; i < 225; i += 128) btS[i] = bt[i * 8 + head];

    const float scale = 0.17677669529663687f;   // 32^-0.5
    #pragma unroll
    for (int i = 0; i < 4; i++) {
        int idx = t + i * 128;
        int row = idx >> 3, c4 = (idx & 7) * 4;
        const float* src = QKV + base + (long)row * 768 + c4;
        float4 q = *(const float4*)(src);
        q.x *= scale; q.y *= scale; q.z *= scale; q.w *= scale;
        *(float4*)&Qs[row * QSTR + c4] = q;
        *(float4*)&Ks[row * QSTR + c4] = *(const float4*)(src + 256);
        *(float4*)&Vs[row * VSTR + c4] = *(const float4*)(src + 512);
    }
    __syncthreads();

    // ---- S = Q@K^T : warp covers key-cols [warp*16, warp*16+16) ----
    float sc[4][2][4];
    #pragma unroll
    for (int mt = 0; mt < 4; mt++)
        #pragma unroll
        for (int nt = 0; nt < 2; nt++)
            #pragma unroll
            for (int i = 0; i < 4; i++) sc[mt][nt][i] = 0.f;

    #pragma unroll
    for (int kt = 0; kt < 4; kt++) {
        uint32_t af[4][4], bf[2][2];
        #pragma unroll
        for (int mt = 0; mt < 4; mt++) {
            int r0 = mt * 16 + gid;
            int c0 = kt * 8 + tig;
            af[mt][0] = __float_as_uint(Qs[r0 * QSTR + c0]);
            af[mt][1] = __float_as_uint(Qs[(r0 + 8) * QSTR + c0]);
            af[mt][2] = __float_as_uint(Qs[r0 * QSTR + c0 + 4]);
            af[mt][3] = __float_as_uint(Qs[(r0 + 8) * QSTR + c0 + 4]);
        }
        #pragma unroll
        for (int nt = 0; nt < 2; nt++) {
            int kr = warp * 16 + nt * 8 + gid;
            int kc = kt * 8 + tig;
            bf[nt][0] = __float_as_uint(Ks[kr * QSTR + kc]);
            bf[nt][1] = __float_as_uint(Ks[kr * QSTR + kc + 4]);
        }
        #pragma unroll
        for (int mt = 0; mt < 4; mt++)
            #pragma unroll
            for (int nt = 0; nt < 2; nt++)
                mma_tf32(sc[mt][nt], af[mt], bf[nt]);
    }

    // ---- bias + shift mask, store S to Ps ----
    int w_in_b = win & 63;
    int wwi = w_in_b >> 3, wwj = w_in_b & 7;
    bool edge = (wwi == 7) || (wwj == 7);
    #pragma unroll
    for (int mt = 0; mt < 4; mt++) {
        #pragma unroll
        for (int half = 0; half < 2; half++) {
            int r = mt * 16 + half * 8 + gid;
            int yi = r >> 3, xi = r & 7;
            int id_i = edge ? bandf(wwi * 8 + yi) * 3 + bandf(wwj * 8 + xi) : 0;
            #pragma unroll
            for (int nt = 0; nt < 2; nt++) {
                int c0 = warp * 16 + nt * 8 + 2 * tig;
                float v0 = sc[mt][nt][half * 2 + 0];
                float v1 = sc[mt][nt][half * 2 + 1];
                #pragma unroll
                for (int j = 0; j < 2; j++) {
                    int c = c0 + j;
                    int yj = c >> 3, xj = c & 7;
                    float add = btS[(yi - yj + 7) * 15 + (xi - xj + 7)];
                    if (edge) {
                        int id_j = bandf(wwi * 8 + yj) * 3 + bandf(wwj * 8 + xj);
                        if (id_i != id_j) add -= 100.f;
                    }
                    if (j == 0) v0 += add; else v1 += add;
                }
                float2 st; st.x = v0; st.y = v1;
                *(float2*)&Ps[r * PSTR + c0] = st;
            }
        }
    }
    __syncthreads();

    // ---- softmax: thread handles half a row ----
    {
        int row = t >> 1;
        int c0 = (t & 1) * 32;
        float4 e[8];
        float mx = -1e30f;
        #pragma unroll
        for (int i = 0; i < 8; i++) {
            e[i] = *(const float4*)&Ps[row * PSTR + c0 + i * 4];
            mx = fmaxf(mx, fmaxf(fmaxf(e[i].x, e[i].y), fmaxf(e[i].z, e[i].w)));
        }
        mx = fmaxf(mx, __shfl_xor_sync(0xffffffffu, mx, 1));
        float sum = 0.f;
        #pragma unroll
        for (int i = 0; i < 8; i++) {
            e[i].x = __expf(e[i].x - mx); e[i].y = __expf(e[i].y - mx);
            e[i].z = __expf(e[i].z - mx); e[i].w = __expf(e[i].w - mx);
            sum += e[i].x + e[i].y + e[i].z + e[i].w;
        }
        sum += __shfl_xor_sync(0xffffffffu, sum, 1);
        float rs = 1.f / sum;
        #pragma unroll
        for (int i = 0; i < 8; i++) {
            e[i].x *= rs; e[i].y *= rs; e[i].z *= rs; e[i].w *= rs;
            *(float4*)&Ps[row * PSTR + c0 + i * 4] = e[i];
        }
    }
    __syncthreads();

    // ---- O = P@V : warp covers query-rows [warp*16, warp*16+16) ----
    float oc[4][4];
    #pragma unroll
    for (int nt = 0; nt < 4; nt++)
        #pragma unroll
        for (int i = 0; i < 4; i++) oc[nt][i] = 0.f;

    #pragma unroll
    for (int kt = 0; kt < 8; kt++) {
        uint32_t af[4], bf[4][2];
        int r0 = warp * 16 + gid;
        int c0 = kt * 8 + tig;
        af[0] = __float_as_uint(Ps[r0 * PSTR + c0]);
        af[1] = __float_as_uint(Ps[(r0 + 8) * PSTR + c0]);
        af[2] = __float_as_uint(Ps[r0 * PSTR + c0 + 4]);
        af[3] = __float_as_uint(Ps[(r0 + 8) * PSTR + c0 + 4]);
        #pragma unroll
        for (int nt = 0; nt < 4; nt++) {
            int vr = kt * 8 + tig;
            int vc = nt * 8 + gid;
            bf[nt][0] = __float_as_uint(Vs[vr * VSTR + vc]);
            bf[nt][1] = __float_as_uint(Vs[(vr + 4) * VSTR + vc]);
        }
        #pragma unroll
        for (int nt = 0; nt < 4; nt++)
            mma_tf32(oc[nt], af, bf[nt]);
    }

    // ---- write O ----
    long obase = ((long)win * 64) * C_DIM + head * 32;
    #pragma unroll
    for (int half = 0; half < 2; half++) {
        int row = warp * 16 + half * 8 + gid;
        #pragma unroll
        for (int nt = 0; nt < 4; nt++) {
            int col = nt * 8 + 2 * tig;
            float2 o;
            o.x = oc[nt][half * 2 + 0];
            o.y = oc[nt][half * 2 + 1];
            *(float2*)(O + obase + (long)row * C_DIM + col) = o;
        }
    }
}

// ---------------------------------------------------------------------------
// Launch
// ---------------------------------------------------------------------------
extern "C" void kernel_launch(void* const* d_in, const int* in_sizes, int n_in,
                              void* d_out, int out_size)
{
    const float* hidden = (const float*)d_in[0];
    const float* ln1_g  = (const float*)d_in[1];
    const float* ln1_b  = (const float*)d_in[2];
    const float* wq     = (const float*)d_in[3];
    const float* bq     = (const float*)d_in[4];
    const float* wk     = (const float*)d_in[5];
    const float* bk     = (const float*)d_in[6];
    const float* wv     = (const float*)d_in[7];
    const float* bv     = (const float*)d_in[8];
    const float* bt     = (const float*)d_in[9];
    const float* wo     = (const float*)d_in[10];
    const float* bo     = (const float*)d_in[11];
    const float* ln2_g  = (const float*)d_in[12];
    const float* ln2_b  = (const float*)d_in[13];
    const float* w1     = (const float*)d_in[14];
    const float* b1     = (const float*)d_in[15];
    const float* w2     = (const float*)d_in[16];
    const float* b2     = (const float*)d_in[17];
    float* out = (float*)d_out;

    float *p_xw, *p_qkv, *p_att, *p_hs, *p_y, *p_mid, *p_wqkv, *p_bqkv;
    cudaGetSymbolAddress((void**)&p_xw,   g_xw);
    cudaGetSymbolAddress((void**)&p_qkv,  g_qkv);
    cudaGetSymbolAddress((void**)&p_att,  g_att);
    cudaGetSymbolAddress((void**)&p_hs,   g_hs);
    cudaGetSymbolAddress((void**)&p_y,    g_y);
    cudaGetSymbolAddress((void**)&p_mid,  g_mid);
    cudaGetSymbolAddress((void**)&p_wqkv, g_wqkv);
    cudaGetSymbolAddress((void**)&p_bqkv, g_bqkv);

    cudaFuncSetAttribute(tf32gemm<0>, cudaFuncAttributeMaxDynamicSharedMemorySize, SMEM_SZ);
    cudaFuncSetAttribute(tf32gemm<1>, cudaFuncAttributeMaxDynamicSharedMemorySize, SMEM_SZ);
    cudaFuncSetAttribute(tf32gemm<2>, cudaFuncAttributeMaxDynamicSharedMemorySize, SMEM_SZ);
    cudaFuncSetAttribute(tf32gemm<3>, cudaFuncAttributeMaxDynamicSharedMemorySize, SMEM_SZ);

    dim3 blk(256);

    pack_qkv<<<768, blk>>>(wq, wk, wv, bq, bk, bv, p_wqkv, p_bqkv);
    ln_kernel<<<M_TOK / 8, blk>>>(hidden, ln1_g, ln1_b, p_xw, 1);
    tf32gemm<0><<<dim3(768 / BN, M_TOK / BM), blk, SMEM_SZ>>>(
        p_xw, p_wqkv, p_bqkv, nullptr, p_qkv, M_TOK, 768, C_DIM,
        nullptr, nullptr, nullptr);
    attn_kernel<<<dim3(2048, 8), dim3(128)>>>(p_qkv, bt, p_att);
    // wo-projection + scatter + residual -> hs, fused LN2 -> y
    tf32gemm<2><<<dim3(C_DIM / BN, M_TOK / BM), blk, SMEM_SZ>>>(
        p_att, wo, bo, hidden, p_hs, M_TOK, C_DIM, C_DIM,
        ln2_g, ln2_b, p_y);
    tf32gemm<1><<<dim3(DFF / BN, M_TOK / BM), blk, SMEM_SZ>>>(
        p_y, w1, b1, nullptr, p_mid, M_TOK, DFF, C_DIM,
        nullptr, nullptr, nullptr);
    tf32gemm<3><<<dim3(C_DIM / BN, M_TOK / BM), blk, SMEM_SZ>>>(
        p_mid, w2, b2, p_hs, out, M_TOK, C_DIM, DFF,
        nullptr, nullptr, nullptr);
}